// round 9
// baseline (speedup 1.0000x reference)
#include <cuda_runtime.h>
#include <cuda_fp16.h>

// Problem constants: B=4, C=64, T=8, H=32, W=32, O=64
#define B_   4
#define TT_  8
#define N_   32          // B*T
#define C_   64
#define HW   1024        // H*W
#define CHW  65536       // C*HW

typedef unsigned long long ull;

// ---------------- f32x2 helpers ----------------
__device__ __forceinline__ ull pack2(float a, float b) {
    ull r;
    asm("mov.b64 %0,{%1,%2};" : "=l"(r) : "f"(a), "f"(b));
    return r;
}
__device__ __forceinline__ void fma2(ull& d, ull a, ull b) {
    asm("fma.rn.f32x2 %0,%1,%2,%0;" : "+l"(d) : "l"(a), "l"(b));
}
__device__ __forceinline__ float2 unpack2(ull v) {
    float2 f;
    asm("mov.b64 {%0,%1},%2;" : "=f"(f.x), "=f"(f.y) : "l"(v));
    return f;
}
__device__ __forceinline__ void f4_to_2ull(float4 v, ull& lo, ull& hi) {
    lo = pack2(v.x, v.y);
    hi = pack2(v.z, v.w);
}

// ---------------- HMMA m16n8k16 fp16->fp32 ----------------
__device__ __forceinline__ void mma16816(float d[4],
    unsigned a0, unsigned a1, unsigned a2, unsigned a3,
    unsigned b0, unsigned b1)
{
    asm volatile(
        "mma.sync.aligned.m16n8k16.row.col.f32.f16.f16.f32 "
        "{%0,%1,%2,%3},{%4,%5,%6,%7},{%8,%9},{%0,%1,%2,%3};"
        : "+f"(d[0]), "+f"(d[1]), "+f"(d[2]), "+f"(d[3])
        : "r"(a0), "r"(a1), "r"(a2), "r"(a3), "r"(b0), "r"(b1));
}

// ---------------- scratch (device globals; no allocation) ----------------
__device__ __half g_qh[N_*HW*C_];               // 4 MB  q fp16, (n,i,c)
__device__ __half g_kh[N_*HW*C_];               // 4 MB  k fp16, (n,i,c)
__device__ float  g_rv [N_*C_*HW];              // 8 MB  v fp32, (n,c,i)
__device__ __half g_rvh[N_*C_*HW];              // 4 MB  v fp16, (n,c,i)
__device__ float  g_gcp[16*N_*C_*C_];           // 8 MB  channel-score partials
__device__ float  g_gc[N_*C_*C_];               // 512 KB softmaxed channel attn
__device__ __half g_ms[(size_t)N_*HW*HW];       // 64 MB exp(spatial scores)
__device__ float  g_inv[HW*HW];                 // 4 MB  1/sum_n exp
__device__ float  g_s [N_*C_*HW];               // 8 MB  a_c + a_s
__device__ float  g_xe[N_*C_*HW];               // 8 MB  relu(tconv3)
__device__ float  g_mtp[B_*8*64];               // temporal score partials
__device__ float  g_mt[B_*TT_*TT_];             // temporal softmax

// ============ K1: one projection per z: relu(W x + b), grid (N_,8,3) ============
__global__ __launch_bounds__(256) void k_qkv(
    const float* __restrict__ x,
    const float* __restrict__ wq, const float* __restrict__ bq,
    const float* __restrict__ wk, const float* __restrict__ bk,
    const float* __restrict__ wv, const float* __restrict__ bv)
{
    extern __shared__ float dyn[];
    float* sx = dyn;            // 64 x 128
    float* sw = dyn + 8192;     // 64o x 64c
    int n = blockIdx.x, b = n >> 3, t = n & 7;
    int i0 = blockIdx.y << 7;
    int p = blockIdx.z;
    int tid = threadIdx.x, ty = tid >> 4, tx = tid & 15;
    int o0 = ty * 4;

    const float* W  = (p == 0) ? wq : (p == 1) ? wk : wv;
    const float* Bb = (p == 0) ? bq : (p == 1) ? bk : bv;

    for (int k = tid; k < 2048; k += 256) {
        int c = k >> 5, f = k & 31;
        ((float4*)sx)[k] =
            ((const float4*)(x + ((size_t)(b*C_ + c)*TT_ + t)*HW + i0))[f];
    }
    for (int k = tid; k < 4096; k += 256) sw[k] = W[k];
    __syncthreads();

    ull acc[4][4];
#pragma unroll
    for (int r = 0; r < 4; r++) {
        float bi = Bb[o0 + r];
        ull bp = pack2(bi, bi);
#pragma unroll
        for (int s = 0; s < 4; s++) acc[r][s] = bp;
    }
#pragma unroll 4
    for (int c = 0; c < C_; c++) {
        ull ap[4];
#pragma unroll
        for (int r = 0; r < 4; r++) {
            float a = sw[(o0 + r)*C_ + c];
            ap[r] = pack2(a, a);
        }
        float4 b0 = *(const float4*)&sx[c*128 + tx*8];
        float4 b1 = *(const float4*)&sx[c*128 + tx*8 + 4];
        ull bv0, bv1, bv2, bv3;
        f4_to_2ull(b0, bv0, bv1);
        f4_to_2ull(b1, bv2, bv3);
#pragma unroll
        for (int r = 0; r < 4; r++) {
            fma2(acc[r][0], ap[r], bv0);
            fma2(acc[r][1], ap[r], bv1);
            fma2(acc[r][2], ap[r], bv2);
            fma2(acc[r][3], ap[r], bv3);
        }
    }
    // unpack + relu
    float va[4][8];
#pragma unroll
    for (int r = 0; r < 4; r++)
#pragma unroll
        for (int s = 0; s < 4; s++) {
            float2 u = unpack2(acc[r][s]);
            va[r][2*s]   = fmaxf(u.x, 0.f);
            va[r][2*s+1] = fmaxf(u.y, 0.f);
        }

    if (p < 2) {
        // q/k -> fp16 (n, i, c) layout
        __half* Oh = (p == 0) ? g_qh : g_kh;
#pragma unroll
        for (int mi = 0; mi < 8; mi++) {
            __half2 h0 = __floats2half2_rn(va[0][mi], va[1][mi]);
            __half2 h1 = __floats2half2_rn(va[2][mi], va[3][mi]);
            uint2 st;
            st.x = *(unsigned*)&h0;
            st.y = *(unsigned*)&h1;
            *(uint2*)(Oh + ((size_t)(n*HW + i0 + tx*8 + mi))*C_ + o0) = st;
        }
    } else {
        // v -> fp32 (n,c,i) + fp16 (n,c,i)
#pragma unroll
        for (int r = 0; r < 4; r++) {
            float* gp = g_rv + (size_t)(n*C_ + o0 + r)*HW + i0 + tx*8;
            *(float4*)gp       = make_float4(va[r][0], va[r][1], va[r][2], va[r][3]);
            *(float4*)(gp + 4) = make_float4(va[r][4], va[r][5], va[r][6], va[r][7]);
            __half2 h0 = __floats2half2_rn(va[r][0], va[r][1]);
            __half2 h1 = __floats2half2_rn(va[r][2], va[r][3]);
            __half2 h2 = __floats2half2_rn(va[r][4], va[r][5]);
            __half2 h3 = __floats2half2_rn(va[r][6], va[r][7]);
            uint4 u;
            u.x = *(unsigned*)&h0; u.y = *(unsigned*)&h1;
            u.z = *(unsigned*)&h2; u.w = *(unsigned*)&h3;
            *(uint4*)(g_rvh + (size_t)(n*C_ + o0 + r)*HW + i0 + tx*8) = u;
        }
    }
}

// ============ K2: channel score partials from fp16 (i,c), grid (N_,16) ============
__global__ __launch_bounds__(256) void k_gc()
{
    int n = blockIdx.x, ic = blockIdx.y;
    int i0 = ic << 6;
    __shared__ float sq[64*68];
    __shared__ float sk[64*68];
    int tid = threadIdx.x, ty = tid >> 4, tx = tid & 15;

    for (int it = 0; it < 2; it++) {
        int idx = tid + it*256;            // 0..511
        int ii = idx >> 3, f = idx & 7;
        uint4 uq = *(const uint4*)(g_qh + ((size_t)(n*HW + i0 + ii))*C_ + f*8);
        uint4 uk = *(const uint4*)(g_kh + ((size_t)(n*HW + i0 + ii))*C_ + f*8);
        const __half2* hq = (const __half2*)&uq;
        const __half2* hk = (const __half2*)&uk;
#pragma unroll
        for (int m = 0; m < 4; m++) {
            float2 fq = __half22float2(hq[m]);
            float2 fk = __half22float2(hk[m]);
            sq[ii*68 + f*8 + 2*m]     = fq.x;
            sq[ii*68 + f*8 + 2*m + 1] = fq.y;
            sk[ii*68 + f*8 + 2*m]     = fk.x;
            sk[ii*68 + f*8 + 2*m + 1] = fk.y;
        }
    }
    __syncthreads();

    float acc[4][4];
#pragma unroll
    for (int r = 0; r < 4; r++)
#pragma unroll
        for (int s = 0; s < 4; s++) acc[r][s] = 0.f;

    for (int ii = 0; ii < 64; ii++) {
        float4 a4 = *(const float4*)&sq[ii*68 + ty*4];
        float4 b4 = *(const float4*)&sk[ii*68 + tx*4];
        float a[4] = {a4.x, a4.y, a4.z, a4.w};
        float bb[4] = {b4.x, b4.y, b4.z, b4.w};
#pragma unroll
        for (int r = 0; r < 4; r++)
#pragma unroll
            for (int s = 0; s < 4; s++) acc[r][s] = fmaf(a[r], bb[s], acc[r][s]);
    }
#pragma unroll
    for (int r = 0; r < 4; r++)
#pragma unroll
        for (int s = 0; s < 4; s++)
            g_gcp[(ic*N_ + n)*4096 + (ty*4 + r)*C_ + tx*4 + s] = acc[r][s];
}

// ============ K3a: reduce 16 partials + softmax over n ============
__global__ void k_gc_softmax()
{
    int cd = blockIdx.x * 256 + threadIdx.x;
    float v[N_];
    float mx = -1e30f;
#pragma unroll
    for (int n = 0; n < N_; n++) {
        float s = 0.f;
#pragma unroll
        for (int ic = 0; ic < 16; ic++) s += g_gcp[(ic*N_ + n)*4096 + cd];
        v[n] = s; mx = fmaxf(mx, s);
    }
    float s = 0.f;
#pragma unroll
    for (int n = 0; n < N_; n++) { v[n] = __expf(v[n] - mx); s += v[n]; }
    float inv = 1.f / s;
#pragma unroll
    for (int n = 0; n < N_; n++) g_gc[n*4096 + cd] = v[n] * inv;
}

// ============ K3b: a_c = m_c @ v (fp32) — FMA2, grid (N_,16) ============
__global__ __launch_bounds__(256) void k_ac()
{
    __shared__ float sv[64*64];
    __shared__ float sm[64*64];
    int n = blockIdx.x;
    int i0 = blockIdx.y << 6;
    int tid = threadIdx.x, ty = tid >> 4, tx = tid & 15;
    int c0 = ty * 4;

    for (int k = tid; k < 1024; k += 256) {
        int d = k >> 4, f = k & 15;
        ((float4*)sv)[k] = ((const float4*)(g_rv + (size_t)(n*C_ + d)*HW + i0))[f];
    }
    for (int k = tid; k < 4096; k += 256) sm[k] = g_gc[n*4096 + k];
    __syncthreads();

    ull acc[4][2];
#pragma unroll
    for (int r = 0; r < 4; r++) { acc[r][0] = 0ULL; acc[r][1] = 0ULL; }

#pragma unroll 8
    for (int d = 0; d < C_; d++) {
        float4 b0 = *(const float4*)&sv[d*64 + tx*4];
        ull bv0, bv1;
        f4_to_2ull(b0, bv0, bv1);
#pragma unroll
        for (int r = 0; r < 4; r++) {
            float a = sm[(c0 + r)*C_ + d];
            ull ap = pack2(a, a);
            fma2(acc[r][0], ap, bv0);
            fma2(acc[r][1], ap, bv1);
        }
    }
#pragma unroll
    for (int r = 0; r < 4; r++) {
        float2 u0 = unpack2(acc[r][0]), u1 = unpack2(acc[r][1]);
        *(float4*)&g_s[(size_t)(n*C_ + c0 + r)*HW + i0 + tx*4] =
            make_float4(u0.x, u0.y, u1.x, u1.y);
    }
}

// ============ K4: e = exp(q^T k) via HMMA — grid (8,8,N_) x 256 ============
// smem: sQ[128][72], sK[128][72] halves (36.9 KB). K=c=64 in one shot.
__global__ __launch_bounds__(256, 2) void k_ms()
{
    __shared__ __half sQ[128*72];
    __shared__ __half sK[128*72];
    int n  = blockIdx.z;
    int i0 = blockIdx.x << 7, j0 = blockIdx.y << 7;
    int tid = threadIdx.x;
    int w = tid >> 5, lane = tid & 31;
    int g = lane >> 2, t = lane & 3;
    int wi = w >> 2, wj = w & 3;            // warp grid 2(i) x 4(j)
    int i_w = wi * 64, j_w = wj * 32;

    for (int it = 0; it < 4; it++) {
        int idx = tid + it*256;             // 0..1023
        int ii = idx >> 3, f = idx & 7;
        *(uint4*)&sQ[ii*72 + f*8] =
            *(const uint4*)(g_qh + ((size_t)(n*HW + i0 + ii))*C_ + f*8);
        *(uint4*)&sK[ii*72 + f*8] =
            *(const uint4*)(g_kh + ((size_t)(n*HW + j0 + ii))*C_ + f*8);
    }
    __syncthreads();

    float acc[4][4][4];                     // [m][nt][4]
#pragma unroll
    for (int m = 0; m < 4; m++)
#pragma unroll
        for (int nt = 0; nt < 4; nt++)
#pragma unroll
            for (int e = 0; e < 4; e++) acc[m][nt][e] = 0.f;

#pragma unroll
    for (int ks = 0; ks < 4; ks++) {
        unsigned a[4][4], bfr[4][2];
#pragma unroll
        for (int m = 0; m < 4; m++) {
            int r0 = i_w + m*16 + g;
            int col = ks*16 + t*2;
            a[m][0] = *(const unsigned*)&sQ[r0*72 + col];
            a[m][1] = *(const unsigned*)&sQ[(r0+8)*72 + col];
            a[m][2] = *(const unsigned*)&sQ[r0*72 + col + 8];
            a[m][3] = *(const unsigned*)&sQ[(r0+8)*72 + col + 8];
        }
#pragma unroll
        for (int nt = 0; nt < 4; nt++) {
            int jr = j_w + nt*8 + g;
            int col = ks*16 + t*2;
            bfr[nt][0] = *(const unsigned*)&sK[jr*72 + col];
            bfr[nt][1] = *(const unsigned*)&sK[jr*72 + col + 8];
        }
#pragma unroll
        for (int m = 0; m < 4; m++)
#pragma unroll
            for (int nt = 0; nt < 4; nt++)
                mma16816(acc[m][nt], a[m][0], a[m][1], a[m][2], a[m][3],
                         bfr[nt][0], bfr[nt][1]);
    }

    __half* outp = g_ms + ((size_t)n << 20);
#pragma unroll
    for (int m = 0; m < 4; m++) {
#pragma unroll
        for (int nt = 0; nt < 4; nt++) {
            int ir0 = i0 + i_w + m*16 + g;
            int j   = j0 + j_w + nt*8 + t*2;
            __half2 h0 = __floats2half2_rn(__expf(acc[m][nt][0]), __expf(acc[m][nt][1]));
            __half2 h1 = __floats2half2_rn(__expf(acc[m][nt][2]), __expf(acc[m][nt][3]));
            *(unsigned*)(outp + (size_t)ir0*HW + j)     = *(unsigned*)&h0;
            *(unsigned*)(outp + (size_t)(ir0+8)*HW + j) = *(unsigned*)&h1;
        }
    }
}

// ============ K5: g_inv = 1 / sum_n e — 8 halves/thread, grid 512 ============
__global__ __launch_bounds__(256) void k_sum()
{
    size_t t = (size_t)blockIdx.x * 256 + threadIdx.x;   // uint4 index, 0..131071
    const uint4* base = (const uint4*)g_ms;
    float2 acc[4];
#pragma unroll
    for (int m = 0; m < 4; m++) acc[m] = make_float2(0.f, 0.f);
#pragma unroll
    for (int n = 0; n < N_; n++) {
        uint4 u = base[((size_t)n << 17) + t];
        const __half2* h = (const __half2*)&u;
#pragma unroll
        for (int m = 0; m < 4; m++) {
            float2 f0 = __half22float2(h[m]);
            acc[m].x += f0.x; acc[m].y += f0.y;
        }
    }
    float* gp = g_inv + t*8;
#pragma unroll
    for (int m = 0; m < 4; m++) {
        gp[2*m]   = 1.f / acc[m].x;
        gp[2*m+1] = 1.f / acc[m].y;
    }
}

// ============ K6: a_s = V @ P^T via HMMA; g_s += — grid (16,N_) x 256 ============
// Block: 64c x 64i, j looped in 16 chunks of 64. smem sV[64][72], sP[64][72].
__global__ __launch_bounds__(256, 4) void k_as()
{
    __shared__ __half sV[64*72];
    __shared__ __half sP[64*72];
    int n  = blockIdx.y;
    int i0 = blockIdx.x << 6;
    int tid = threadIdx.x;
    int w = tid >> 5, lane = tid & 31;
    int g = lane >> 2, t = lane & 3;
    int wc = w >> 2, wi = w & 3;            // warp grid 2(c) x 4(i)
    int c_w = wc * 32, i_w = wi * 16;

    float acc[2][2][4];                     // [m][nt][4]
#pragma unroll
    for (int m = 0; m < 2; m++)
#pragma unroll
        for (int nt = 0; nt < 2; nt++)
#pragma unroll
            for (int e = 0; e < 4; e++) acc[m][nt][e] = 0.f;

    const __half* msph = g_ms + ((size_t)n << 20);
    for (int jc = 0; jc < 16; jc++) {
        int j0 = jc << 6;
        __syncthreads();
        for (int it = 0; it < 2; it++) {
            int idx = tid + it*256;         // 0..511
            int row = idx >> 3, f = idx & 7;
            // V tile
            *(uint4*)&sV[row*72 + f*8] =
                *(const uint4*)(g_rvh + (size_t)(n*C_ + row)*HW + j0 + f*8);
            // P tile = e * inv
            int gi = i0 + row;
            uint4 ue = *(const uint4*)(msph + (size_t)gi*HW + j0 + f*8);
            const __half2* he = (const __half2*)&ue;
            const float4* ip = (const float4*)&g_inv[gi*HW + j0 + f*8];
            float4 iv0 = ip[0], iv1 = ip[1];
            float2 e0 = __half22float2(he[0]);
            float2 e1 = __half22float2(he[1]);
            float2 e2 = __half22float2(he[2]);
            float2 e3 = __half22float2(he[3]);
            __half2 p0 = __floats2half2_rn(e0.x*iv0.x, e0.y*iv0.y);
            __half2 p1 = __floats2half2_rn(e1.x*iv0.z, e1.y*iv0.w);
            __half2 p2 = __floats2half2_rn(e2.x*iv1.x, e2.y*iv1.y);
            __half2 p3 = __floats2half2_rn(e3.x*iv1.z, e3.y*iv1.w);
            uint4 up;
            up.x = *(unsigned*)&p0; up.y = *(unsigned*)&p1;
            up.z = *(unsigned*)&p2; up.w = *(unsigned*)&p3;
            *(uint4*)&sP[row*72 + f*8] = up;
        }
        __syncthreads();

#pragma unroll
        for (int ks = 0; ks < 4; ks++) {
            unsigned a[2][4], bfr[2][2];
            int col = ks*16 + t*2;
#pragma unroll
            for (int m = 0; m < 2; m++) {
                int r0 = c_w + m*16 + g;
                a[m][0] = *(const unsigned*)&sV[r0*72 + col];
                a[m][1] = *(const unsigned*)&sV[(r0+8)*72 + col];
                a[m][2] = *(const unsigned*)&sV[r0*72 + col + 8];
                a[m][3] = *(const unsigned*)&sV[(r0+8)*72 + col + 8];
            }
#pragma unroll
            for (int nt = 0; nt < 2; nt++) {
                int ir = i_w + nt*8 + g;
                bfr[nt][0] = *(const unsigned*)&sP[ir*72 + col];
                bfr[nt][1] = *(const unsigned*)&sP[ir*72 + col + 8];
            }
#pragma unroll
            for (int m = 0; m < 2; m++)
#pragma unroll
                for (int nt = 0; nt < 2; nt++)
                    mma16816(acc[m][nt], a[m][0], a[m][1], a[m][2], a[m][3],
                             bfr[nt][0], bfr[nt][1]);
        }
    }

    // accumulate into g_s (holds a_c); disjoint tiles -> no races
#pragma unroll
    for (int m = 0; m < 2; m++) {
#pragma unroll
        for (int nt = 0; nt < 2; nt++) {
            int c0 = c_w + m*16 + g;
            int i  = i0 + i_w + nt*8 + t*2;
            float2* p0 = (float2*)&g_s[(size_t)(n*C_ + c0)*HW + i];
            float2 v0 = *p0;
            v0.x += acc[m][nt][0]; v0.y += acc[m][nt][1];
            *p0 = v0;
            float2* p1 = (float2*)&g_s[(size_t)(n*C_ + c0 + 8)*HW + i];
            float2 v1 = *p1;
            v1.x += acc[m][nt][2]; v1.y += acc[m][nt][3];
            *p1 = v1;
        }
    }
}

// ============ K7: Xe = relu(tconv3(g_s)) — FMA2, grid (N_,8) ============
__global__ __launch_bounds__(256) void k_tconv(const float* __restrict__ wX,
                                               const float* __restrict__ bX)
{
    __shared__ float sw[4096];
    __shared__ float ss[32*128];
    int n = blockIdx.x, b = n >> 3, t = n & 7;
    int i0 = blockIdx.y << 7;
    int tid = threadIdx.x, ty = tid >> 4, tx = tid & 15;
    int o0 = ty * 4;

    ull acc[4][4];
#pragma unroll
    for (int r = 0; r < 4; r++) {
        float bi = bX[o0 + r];
        ull bp = pack2(bi, bi);
#pragma unroll
        for (int s = 0; s < 4; s++) acc[r][s] = bp;
    }

    for (int kt = 0; kt < 3; kt++) {
        int t2 = t + kt - 1;
        if (t2 < 0 || t2 >= TT_) continue;
        __syncthreads();
        for (int k = tid; k < 4096; k += 256) sw[k] = wX[k*3 + kt];
        for (int cc = 0; cc < 2; cc++) {
            __syncthreads();
            size_t off = (size_t)((b*TT_ + t2)*C_ + cc*32)*HW + i0;
            for (int k = tid; k < 1024; k += 256) {
                int c = k >> 5, f = k & 31;
                ((float4*)ss)[k] = ((const float4*)(g_s + off + c*HW))[f];
            }
            __syncthreads();
#pragma unroll 4
            for (int c = 0; c < 32; c++) {
                ull ap[4];
#pragma unroll
                for (int r = 0; r < 4; r++) {
                    float a = sw[(o0 + r)*C_ + cc*32 + c];
                    ap[r] = pack2(a, a);
                }
                float4 b0 = *(const float4*)&ss[c*128 + tx*8];
                float4 b1 = *(const float4*)&ss[c*128 + tx*8 + 4];
                ull bv0, bv1, bv2, bv3;
                f4_to_2ull(b0, bv0, bv1);
                f4_to_2ull(b1, bv2, bv3);
#pragma unroll
                for (int r = 0; r < 4; r++) {
                    fma2(acc[r][0], ap[r], bv0);
                    fma2(acc[r][1], ap[r], bv1);
                    fma2(acc[r][2], ap[r], bv2);
                    fma2(acc[r][3], ap[r], bv3);
                }
            }
        }
    }
#pragma unroll
    for (int r = 0; r < 4; r++) {
        float2 u0 = unpack2(acc[r][0]), u1 = unpack2(acc[r][1]);
        float2 u2 = unpack2(acc[r][2]), u3 = unpack2(acc[r][3]);
        float* gp = g_xe + (size_t)(n*C_ + o0 + r)*HW + i0 + tx*8;
        *(float4*)gp       = make_float4(fmaxf(u0.x,0.f), fmaxf(u0.y,0.f),
                                         fmaxf(u1.x,0.f), fmaxf(u1.y,0.f));
        *(float4*)(gp + 4) = make_float4(fmaxf(u2.x,0.f), fmaxf(u2.y,0.f),
                                         fmaxf(u3.x,0.f), fmaxf(u3.y,0.f));
    }
}

// ============ K8a: temporal score partials, grid (B_,8) ============
__global__ __launch_bounds__(256) void k_mtp()
{
    int b = blockIdx.x, dc = blockIdx.y;
    int tid = threadIdx.x, lane = tid & 31, warp = tid >> 5;
    int d0 = dc * 8192;
    float acc[64];
#pragma unroll
    for (int a = 0; a < 64; a++) acc[a] = 0.f;

    for (int m = 0; m < 32; m++) {
        int d = d0 + m*256 + tid;
        float v[8];
#pragma unroll
        for (int t = 0; t < 8; t++) v[t] = g_xe[(size_t)(b*TT_ + t)*CHW + d];
#pragma unroll
        for (int t = 0; t < 8; t++)
#pragma unroll
            for (int s = 0; s < 8; s++) acc[t*8 + s] = fmaf(v[t], v[s], acc[t*8 + s]);
    }
#pragma unroll
    for (int a = 0; a < 64; a++) {
#pragma unroll
        for (int off = 16; off > 0; off >>= 1)
            acc[a] += __shfl_xor_sync(0xffffffffu, acc[a], off);
    }
    __shared__ float red[8][64];
    if (lane == 0)
        for (int a = 0; a < 64; a++) red[warp][a] = acc[a];
    __syncthreads();
    if (tid < 64) {
        float s = 0.f;
#pragma unroll
        for (int w = 0; w < 8; w++) s += red[w][tid];
        g_mtp[(b*8 + dc)*64 + tid] = s;
    }
}

// ============ K8b: reduce partials + softmax over b ============
__global__ void k_mt_softmax()
{
    __shared__ float sm[B_][64];
    int tid = threadIdx.x;
    int b = tid >> 6, ts = tid & 63;
    float s = 0.f;
#pragma unroll
    for (int dc = 0; dc < 8; dc++) s += g_mtp[(b*8 + dc)*64 + ts];
    sm[b][ts] = s;
    __syncthreads();
    if (tid < 64) {
        float v[B_];
        float mx = -1e30f;
#pragma unroll
        for (int bb = 0; bb < B_; bb++) { v[bb] = sm[bb][tid]; mx = fmaxf(mx, v[bb]); }
        float ss = 0.f;
#pragma unroll
        for (int bb = 0; bb < B_; bb++) { v[bb] = __expf(v[bb] - mx); ss += v[bb]; }
        float inv = 1.f / ss;
#pragma unroll
        for (int bb = 0; bb < B_; bb++) g_mt[bb*64 + tid] = v[bb] * inv;
    }
}

// ============ K8c: out[b,c,t,i] = sum_s m_t[b,t,s] v[b,s,c,i], grid 256 ============
__global__ __launch_bounds__(256) void k_out(float* __restrict__ out)
{
    int bc = blockIdx.x;
    int b = bc >> 6, c = bc & 63;
    __shared__ float smt[64];
    if (threadIdx.x < 64) smt[threadIdx.x] = g_mt[b*64 + threadIdx.x];
    __syncthreads();
    for (int k = 0; k < 4; k++) {
        int i = k*256 + threadIdx.x;
        float v[8];
#pragma unroll
        for (int s = 0; s < 8; s++)
            v[s] = g_rv[(size_t)((b*TT_ + s)*C_ + c)*HW + i];
#pragma unroll
        for (int t = 0; t < 8; t++) {
            float a = 0.f;
#pragma unroll
            for (int s = 0; s < 8; s++) a = fmaf(smt[t*8 + s], v[s], a);
            out[(size_t)((b*C_ + c)*TT_ + t)*HW + i] = a;
        }
    }
}

// ---------------- launch ----------------
extern "C" void kernel_launch(void* const* d_in, const int* in_sizes, int n_in,
                              void* d_out, int out_size)
{
    const float* x  = (const float*)d_in[0];
    const float* wq = (const float*)d_in[1];
    const float* bq = (const float*)d_in[2];
    const float* wk = (const float*)d_in[3];
    const float* bk = (const float*)d_in[4];
    const float* wv = (const float*)d_in[5];
    const float* bv = (const float*)d_in[6];
    const float* wX = (const float*)d_in[7];
    const float* bX = (const float*)d_in[8];
    float* out = (float*)d_out;
    (void)in_sizes; (void)n_in; (void)out_size;

    cudaFuncSetAttribute(k_qkv, cudaFuncAttributeMaxDynamicSharedMemorySize, 49152);

    k_qkv<<<dim3(N_, 8, 3), 256, 49152>>>(x, wq, bq, wk, bk, wv, bv);
    k_gc<<<dim3(N_, 16), 256>>>();
    k_gc_softmax<<<16, 256>>>();
    k_ac<<<dim3(N_, 16), 256>>>();
    k_ms<<<dim3(8, 8, N_), 256>>>();
    k_sum<<<512, 256>>>();
    k_as<<<dim3(16, N_), 256>>>();
    k_tconv<<<dim3(N_, 8), 256>>>(wX, bX);
    k_mtp<<<dim3(B_, 8), 256>>>();
    k_mt_softmax<<<1, 256>>>();
    k_out<<<256, 256>>>(out);
}

// round 10
// speedup vs baseline: 1.0006x; 1.0006x over previous
#include <cuda_runtime.h>
#include <cuda_fp16.h>

// Problem constants: B=4, C=64, T=8, H=32, W=32, O=64
#define B_   4
#define TT_  8
#define N_   32          // B*T
#define C_   64
#define HW   1024        // H*W
#define CHW  65536       // C*HW

typedef unsigned long long ull;

// ---------------- f32x2 helpers ----------------
__device__ __forceinline__ ull pack2(float a, float b) {
    ull r;
    asm("mov.b64 %0,{%1,%2};" : "=l"(r) : "f"(a), "f"(b));
    return r;
}
__device__ __forceinline__ void fma2(ull& d, ull a, ull b) {
    asm("fma.rn.f32x2 %0,%1,%2,%0;" : "+l"(d) : "l"(a), "l"(b));
}
__device__ __forceinline__ float2 unpack2(ull v) {
    float2 f;
    asm("mov.b64 {%0,%1},%2;" : "=f"(f.x), "=f"(f.y) : "l"(v));
    return f;
}
__device__ __forceinline__ void f4_to_2ull(float4 v, ull& lo, ull& hi) {
    lo = pack2(v.x, v.y);
    hi = pack2(v.z, v.w);
}

// ---------------- HMMA m16n8k16 fp16->fp32 ----------------
__device__ __forceinline__ void mma16816(float d[4],
    unsigned a0, unsigned a1, unsigned a2, unsigned a3,
    unsigned b0, unsigned b1)
{
    asm volatile(
        "mma.sync.aligned.m16n8k16.row.col.f32.f16.f16.f32 "
        "{%0,%1,%2,%3},{%4,%5,%6,%7},{%8,%9},{%0,%1,%2,%3};"
        : "+f"(d[0]), "+f"(d[1]), "+f"(d[2]), "+f"(d[3])
        : "r"(a0), "r"(a1), "r"(a2), "r"(a3), "r"(b0), "r"(b1));
}

// ---------------- scratch (device globals; no allocation) ----------------
__device__ __half g_qh[N_*HW*C_];               // 4 MB  q fp16, (n,i,c)
__device__ __half g_kh[N_*HW*C_];               // 4 MB  k fp16, (n,i,c)
__device__ float  g_rv [N_*C_*HW];              // 8 MB  v fp32, (n,c,i)
__device__ __half g_rvh[N_*C_*HW];              // 4 MB  v fp16, (n,c,i)
__device__ float  g_gcp[16*N_*C_*C_];           // 8 MB  channel-score partials
__device__ float  g_gc[N_*C_*C_];               // 512 KB softmaxed channel attn
__device__ __half g_ms[(size_t)N_*HW*HW];       // 64 MB exp(spatial scores)
__device__ float  g_inv[HW*HW];                 // 4 MB  1/sum_n exp
__device__ float  g_s [N_*C_*HW];               // 8 MB  a_c + a_s
__device__ float  g_xe[N_*C_*HW];               // 8 MB  relu(tconv3)
__device__ float  g_mtp[B_*8*64];               // temporal score partials
__device__ float  g_mt[B_*TT_*TT_];             // temporal softmax

// ============ K1: one projection per z: relu(W x + b), grid (N_,8,3) ============
__global__ __launch_bounds__(256) void k_qkv(
    const float* __restrict__ x,
    const float* __restrict__ wq, const float* __restrict__ bq,
    const float* __restrict__ wk, const float* __restrict__ bk,
    const float* __restrict__ wv, const float* __restrict__ bv)
{
    extern __shared__ float dyn[];
    float* sx = dyn;            // 64 x 128
    float* sw = dyn + 8192;     // 64o x 64c
    int n = blockIdx.x, b = n >> 3, t = n & 7;
    int i0 = blockIdx.y << 7;
    int p = blockIdx.z;
    int tid = threadIdx.x, ty = tid >> 4, tx = tid & 15;
    int o0 = ty * 4;

    const float* W  = (p == 0) ? wq : (p == 1) ? wk : wv;
    const float* Bb = (p == 0) ? bq : (p == 1) ? bk : bv;

    for (int k = tid; k < 2048; k += 256) {
        int c = k >> 5, f = k & 31;
        ((float4*)sx)[k] =
            ((const float4*)(x + ((size_t)(b*C_ + c)*TT_ + t)*HW + i0))[f];
    }
    for (int k = tid; k < 4096; k += 256) sw[k] = W[k];
    __syncthreads();

    ull acc[4][4];
#pragma unroll
    for (int r = 0; r < 4; r++) {
        float bi = Bb[o0 + r];
        ull bp = pack2(bi, bi);
#pragma unroll
        for (int s = 0; s < 4; s++) acc[r][s] = bp;
    }
#pragma unroll 4
    for (int c = 0; c < C_; c++) {
        ull ap[4];
#pragma unroll
        for (int r = 0; r < 4; r++) {
            float a = sw[(o0 + r)*C_ + c];
            ap[r] = pack2(a, a);
        }
        float4 b0 = *(const float4*)&sx[c*128 + tx*8];
        float4 b1 = *(const float4*)&sx[c*128 + tx*8 + 4];
        ull bv0, bv1, bv2, bv3;
        f4_to_2ull(b0, bv0, bv1);
        f4_to_2ull(b1, bv2, bv3);
#pragma unroll
        for (int r = 0; r < 4; r++) {
            fma2(acc[r][0], ap[r], bv0);
            fma2(acc[r][1], ap[r], bv1);
            fma2(acc[r][2], ap[r], bv2);
            fma2(acc[r][3], ap[r], bv3);
        }
    }
    // unpack + relu
    float va[4][8];
#pragma unroll
    for (int r = 0; r < 4; r++)
#pragma unroll
        for (int s = 0; s < 4; s++) {
            float2 u = unpack2(acc[r][s]);
            va[r][2*s]   = fmaxf(u.x, 0.f);
            va[r][2*s+1] = fmaxf(u.y, 0.f);
        }

    if (p < 2) {
        // q/k -> fp16 (n, i, c) layout
        __half* Oh = (p == 0) ? g_qh : g_kh;
#pragma unroll
        for (int mi = 0; mi < 8; mi++) {
            __half2 h0 = __floats2half2_rn(va[0][mi], va[1][mi]);
            __half2 h1 = __floats2half2_rn(va[2][mi], va[3][mi]);
            uint2 st;
            st.x = *(unsigned*)&h0;
            st.y = *(unsigned*)&h1;
            *(uint2*)(Oh + ((size_t)(n*HW + i0 + tx*8 + mi))*C_ + o0) = st;
        }
    } else {
        // v -> fp32 (n,c,i) + fp16 (n,c,i)
#pragma unroll
        for (int r = 0; r < 4; r++) {
            float* gp = g_rv + (size_t)(n*C_ + o0 + r)*HW + i0 + tx*8;
            *(float4*)gp       = make_float4(va[r][0], va[r][1], va[r][2], va[r][3]);
            *(float4*)(gp + 4) = make_float4(va[r][4], va[r][5], va[r][6], va[r][7]);
            __half2 h0 = __floats2half2_rn(va[r][0], va[r][1]);
            __half2 h1 = __floats2half2_rn(va[r][2], va[r][3]);
            __half2 h2 = __floats2half2_rn(va[r][4], va[r][5]);
            __half2 h3 = __floats2half2_rn(va[r][6], va[r][7]);
            uint4 u;
            u.x = *(unsigned*)&h0; u.y = *(unsigned*)&h1;
            u.z = *(unsigned*)&h2; u.w = *(unsigned*)&h3;
            *(uint4*)(g_rvh + (size_t)(n*C_ + o0 + r)*HW + i0 + tx*8) = u;
        }
    }
}

// ============ K2: channel score partials from fp16 (i,c), grid (N_,16) ============
__global__ __launch_bounds__(256) void k_gc()
{
    int n = blockIdx.x, ic = blockIdx.y;
    int i0 = ic << 6;
    __shared__ float sq[64*68];
    __shared__ float sk[64*68];
    int tid = threadIdx.x, ty = tid >> 4, tx = tid & 15;

    for (int it = 0; it < 2; it++) {
        int idx = tid + it*256;            // 0..511
        int ii = idx >> 3, f = idx & 7;
        uint4 uq = *(const uint4*)(g_qh + ((size_t)(n*HW + i0 + ii))*C_ + f*8);
        uint4 uk = *(const uint4*)(g_kh + ((size_t)(n*HW + i0 + ii))*C_ + f*8);
        const __half2* hq = (const __half2*)&uq;
        const __half2* hk = (const __half2*)&uk;
#pragma unroll
        for (int m = 0; m < 4; m++) {
            float2 fq = __half22float2(hq[m]);
            float2 fk = __half22float2(hk[m]);
            sq[ii*68 + f*8 + 2*m]     = fq.x;
            sq[ii*68 + f*8 + 2*m + 1] = fq.y;
            sk[ii*68 + f*8 + 2*m]     = fk.x;
            sk[ii*68 + f*8 + 2*m + 1] = fk.y;
        }
    }
    __syncthreads();

    float acc[4][4];
#pragma unroll
    for (int r = 0; r < 4; r++)
#pragma unroll
        for (int s = 0; s < 4; s++) acc[r][s] = 0.f;

    for (int ii = 0; ii < 64; ii++) {
        float4 a4 = *(const float4*)&sq[ii*68 + ty*4];
        float4 b4 = *(const float4*)&sk[ii*68 + tx*4];
        float a[4] = {a4.x, a4.y, a4.z, a4.w};
        float bb[4] = {b4.x, b4.y, b4.z, b4.w};
#pragma unroll
        for (int r = 0; r < 4; r++)
#pragma unroll
            for (int s = 0; s < 4; s++) acc[r][s] = fmaf(a[r], bb[s], acc[r][s]);
    }
#pragma unroll
    for (int r = 0; r < 4; r++)
#pragma unroll
        for (int s = 0; s < 4; s++)
            g_gcp[(ic*N_ + n)*4096 + (ty*4 + r)*C_ + tx*4 + s] = acc[r][s];
}

// ============ K3a: reduce 16 partials + softmax over n ============
__global__ void k_gc_softmax()
{
    int cd = blockIdx.x * 256 + threadIdx.x;
    float v[N_];
    float mx = -1e30f;
#pragma unroll
    for (int n = 0; n < N_; n++) {
        float s = 0.f;
#pragma unroll
        for (int ic = 0; ic < 16; ic++) s += g_gcp[(ic*N_ + n)*4096 + cd];
        v[n] = s; mx = fmaxf(mx, s);
    }
    float s = 0.f;
#pragma unroll
    for (int n = 0; n < N_; n++) { v[n] = __expf(v[n] - mx); s += v[n]; }
    float inv = 1.f / s;
#pragma unroll
    for (int n = 0; n < N_; n++) g_gc[n*4096 + cd] = v[n] * inv;
}

// ============ K3b: a_c = m_c @ v (fp32) — FMA2, grid (N_,16) ============
__global__ __launch_bounds__(256) void k_ac()
{
    __shared__ float sv[64*64];
    __shared__ float sm[64*64];
    int n = blockIdx.x;
    int i0 = blockIdx.y << 6;
    int tid = threadIdx.x, ty = tid >> 4, tx = tid & 15;
    int c0 = ty * 4;

    for (int k = tid; k < 1024; k += 256) {
        int d = k >> 4, f = k & 15;
        ((float4*)sv)[k] = ((const float4*)(g_rv + (size_t)(n*C_ + d)*HW + i0))[f];
    }
    for (int k = tid; k < 4096; k += 256) sm[k] = g_gc[n*4096 + k];
    __syncthreads();

    ull acc[4][2];
#pragma unroll
    for (int r = 0; r < 4; r++) { acc[r][0] = 0ULL; acc[r][1] = 0ULL; }

#pragma unroll 8
    for (int d = 0; d < C_; d++) {
        float4 b0 = *(const float4*)&sv[d*64 + tx*4];
        ull bv0, bv1;
        f4_to_2ull(b0, bv0, bv1);
#pragma unroll
        for (int r = 0; r < 4; r++) {
            float a = sm[(c0 + r)*C_ + d];
            ull ap = pack2(a, a);
            fma2(acc[r][0], ap, bv0);
            fma2(acc[r][1], ap, bv1);
        }
    }
#pragma unroll
    for (int r = 0; r < 4; r++) {
        float2 u0 = unpack2(acc[r][0]), u1 = unpack2(acc[r][1]);
        *(float4*)&g_s[(size_t)(n*C_ + c0 + r)*HW + i0 + tx*4] =
            make_float4(u0.x, u0.y, u1.x, u1.y);
    }
}

// ============ K4: e = exp(q^T k) via HMMA — grid (8,8,N_) x 256 ============
// smem: sQ[128][72], sK[128][72] halves (36.9 KB). K=c=64 in one shot.
__global__ __launch_bounds__(256, 2) void k_ms()
{
    __shared__ __half sQ[128*72];
    __shared__ __half sK[128*72];
    int n  = blockIdx.z;
    int i0 = blockIdx.x << 7, j0 = blockIdx.y << 7;
    int tid = threadIdx.x;
    int w = tid >> 5, lane = tid & 31;
    int g = lane >> 2, t = lane & 3;
    int wi = w >> 2, wj = w & 3;            // warp grid 2(i) x 4(j)
    int i_w = wi * 64, j_w = wj * 32;

    for (int it = 0; it < 4; it++) {
        int idx = tid + it*256;             // 0..1023
        int ii = idx >> 3, f = idx & 7;
        *(uint4*)&sQ[ii*72 + f*8] =
            *(const uint4*)(g_qh + ((size_t)(n*HW + i0 + ii))*C_ + f*8);
        *(uint4*)&sK[ii*72 + f*8] =
            *(const uint4*)(g_kh + ((size_t)(n*HW + j0 + ii))*C_ + f*8);
    }
    __syncthreads();

    float acc[4][4][4];                     // [m][nt][4]
#pragma unroll
    for (int m = 0; m < 4; m++)
#pragma unroll
        for (int nt = 0; nt < 4; nt++)
#pragma unroll
            for (int e = 0; e < 4; e++) acc[m][nt][e] = 0.f;

#pragma unroll
    for (int ks = 0; ks < 4; ks++) {
        unsigned a[4][4], bfr[4][2];
#pragma unroll
        for (int m = 0; m < 4; m++) {
            int r0 = i_w + m*16 + g;
            int col = ks*16 + t*2;
            a[m][0] = *(const unsigned*)&sQ[r0*72 + col];
            a[m][1] = *(const unsigned*)&sQ[(r0+8)*72 + col];
            a[m][2] = *(const unsigned*)&sQ[r0*72 + col + 8];
            a[m][3] = *(const unsigned*)&sQ[(r0+8)*72 + col + 8];
        }
#pragma unroll
        for (int nt = 0; nt < 4; nt++) {
            int jr = j_w + nt*8 + g;
            int col = ks*16 + t*2;
            bfr[nt][0] = *(const unsigned*)&sK[jr*72 + col];
            bfr[nt][1] = *(const unsigned*)&sK[jr*72 + col + 8];
        }
#pragma unroll
        for (int m = 0; m < 4; m++)
#pragma unroll
            for (int nt = 0; nt < 4; nt++)
                mma16816(acc[m][nt], a[m][0], a[m][1], a[m][2], a[m][3],
                         bfr[nt][0], bfr[nt][1]);
    }

    __half* outp = g_ms + ((size_t)n << 20);
#pragma unroll
    for (int m = 0; m < 4; m++) {
#pragma unroll
        for (int nt = 0; nt < 4; nt++) {
            int ir0 = i0 + i_w + m*16 + g;
            int j   = j0 + j_w + nt*8 + t*2;
            __half2 h0 = __floats2half2_rn(__expf(acc[m][nt][0]), __expf(acc[m][nt][1]));
            __half2 h1 = __floats2half2_rn(__expf(acc[m][nt][2]), __expf(acc[m][nt][3]));
            *(unsigned*)(outp + (size_t)ir0*HW + j)     = *(unsigned*)&h0;
            *(unsigned*)(outp + (size_t)(ir0+8)*HW + j) = *(unsigned*)&h1;
        }
    }
}

// ============ K5: g_inv = 1 / sum_n e — 8 halves/thread, grid 512 ============
__global__ __launch_bounds__(256) void k_sum()
{
    size_t t = (size_t)blockIdx.x * 256 + threadIdx.x;   // uint4 index, 0..131071
    const uint4* base = (const uint4*)g_ms;
    float2 acc[4];
#pragma unroll
    for (int m = 0; m < 4; m++) acc[m] = make_float2(0.f, 0.f);
#pragma unroll
    for (int n = 0; n < N_; n++) {
        uint4 u = base[((size_t)n << 17) + t];
        const __half2* h = (const __half2*)&u;
#pragma unroll
        for (int m = 0; m < 4; m++) {
            float2 f0 = __half22float2(h[m]);
            acc[m].x += f0.x; acc[m].y += f0.y;
        }
    }
    float* gp = g_inv + t*8;
#pragma unroll
    for (int m = 0; m < 4; m++) {
        gp[2*m]   = 1.f / acc[m].x;
        gp[2*m+1] = 1.f / acc[m].y;
    }
}

// ============ K6: a_s = V @ P^T via HMMA; g_s += — grid (16,N_) x 256 ============
// Block: 64c x 64i, j looped in 16 chunks of 64. smem sV[64][72], sP[64][72].
__global__ __launch_bounds__(256, 4) void k_as()
{
    __shared__ __half sV[64*72];
    __shared__ __half sP[64*72];
    int n  = blockIdx.y;
    int i0 = blockIdx.x << 6;
    int tid = threadIdx.x;
    int w = tid >> 5, lane = tid & 31;
    int g = lane >> 2, t = lane & 3;
    int wc = w >> 2, wi = w & 3;            // warp grid 2(c) x 4(i)
    int c_w = wc * 32, i_w = wi * 16;

    float acc[2][2][4];                     // [m][nt][4]
#pragma unroll
    for (int m = 0; m < 2; m++)
#pragma unroll
        for (int nt = 0; nt < 2; nt++)
#pragma unroll
            for (int e = 0; e < 4; e++) acc[m][nt][e] = 0.f;

    const __half* msph = g_ms + ((size_t)n << 20);
    for (int jc = 0; jc < 16; jc++) {
        int j0 = jc << 6;
        __syncthreads();
        for (int it = 0; it < 2; it++) {
            int idx = tid + it*256;         // 0..511
            int row = idx >> 3, f = idx & 7;
            // V tile
            *(uint4*)&sV[row*72 + f*8] =
                *(const uint4*)(g_rvh + (size_t)(n*C_ + row)*HW + j0 + f*8);
            // P tile = e * inv
            int gi = i0 + row;
            uint4 ue = *(const uint4*)(msph + (size_t)gi*HW + j0 + f*8);
            const __half2* he = (const __half2*)&ue;
            const float4* ip = (const float4*)&g_inv[gi*HW + j0 + f*8];
            float4 iv0 = ip[0], iv1 = ip[1];
            float2 e0 = __half22float2(he[0]);
            float2 e1 = __half22float2(he[1]);
            float2 e2 = __half22float2(he[2]);
            float2 e3 = __half22float2(he[3]);
            __half2 p0 = __floats2half2_rn(e0.x*iv0.x, e0.y*iv0.y);
            __half2 p1 = __floats2half2_rn(e1.x*iv0.z, e1.y*iv0.w);
            __half2 p2 = __floats2half2_rn(e2.x*iv1.x, e2.y*iv1.y);
            __half2 p3 = __floats2half2_rn(e3.x*iv1.z, e3.y*iv1.w);
            uint4 up;
            up.x = *(unsigned*)&p0; up.y = *(unsigned*)&p1;
            up.z = *(unsigned*)&p2; up.w = *(unsigned*)&p3;
            *(uint4*)&sP[row*72 + f*8] = up;
        }
        __syncthreads();

#pragma unroll
        for (int ks = 0; ks < 4; ks++) {
            unsigned a[2][4], bfr[2][2];
            int col = ks*16 + t*2;
#pragma unroll
            for (int m = 0; m < 2; m++) {
                int r0 = c_w + m*16 + g;
                a[m][0] = *(const unsigned*)&sV[r0*72 + col];
                a[m][1] = *(const unsigned*)&sV[(r0+8)*72 + col];
                a[m][2] = *(const unsigned*)&sV[r0*72 + col + 8];
                a[m][3] = *(const unsigned*)&sV[(r0+8)*72 + col + 8];
            }
#pragma unroll
            for (int nt = 0; nt < 2; nt++) {
                int ir = i_w + nt*8 + g;
                bfr[nt][0] = *(const unsigned*)&sP[ir*72 + col];
                bfr[nt][1] = *(const unsigned*)&sP[ir*72 + col + 8];
            }
#pragma unroll
            for (int m = 0; m < 2; m++)
#pragma unroll
                for (int nt = 0; nt < 2; nt++)
                    mma16816(acc[m][nt], a[m][0], a[m][1], a[m][2], a[m][3],
                             bfr[nt][0], bfr[nt][1]);
        }
    }

    // accumulate into g_s (holds a_c); disjoint tiles -> no races
#pragma unroll
    for (int m = 0; m < 2; m++) {
#pragma unroll
        for (int nt = 0; nt < 2; nt++) {
            int c0 = c_w + m*16 + g;
            int i  = i0 + i_w + nt*8 + t*2;
            float2* p0 = (float2*)&g_s[(size_t)(n*C_ + c0)*HW + i];
            float2 v0 = *p0;
            v0.x += acc[m][nt][0]; v0.y += acc[m][nt][1];
            *p0 = v0;
            float2* p1 = (float2*)&g_s[(size_t)(n*C_ + c0 + 8)*HW + i];
            float2 v1 = *p1;
            v1.x += acc[m][nt][2]; v1.y += acc[m][nt][3];
            *p1 = v1;
        }
    }
}

// ============ K7: Xe = relu(tconv3(g_s)) — FMA2, grid (N_,8) ============
__global__ __launch_bounds__(256) void k_tconv(const float* __restrict__ wX,
                                               const float* __restrict__ bX)
{
    __shared__ float sw[4096];
    __shared__ float ss[32*128];
    int n = blockIdx.x, b = n >> 3, t = n & 7;
    int i0 = blockIdx.y << 7;
    int tid = threadIdx.x, ty = tid >> 4, tx = tid & 15;
    int o0 = ty * 4;

    ull acc[4][4];
#pragma unroll
    for (int r = 0; r < 4; r++) {
        float bi = bX[o0 + r];
        ull bp = pack2(bi, bi);
#pragma unroll
        for (int s = 0; s < 4; s++) acc[r][s] = bp;
    }

    for (int kt = 0; kt < 3; kt++) {
        int t2 = t + kt - 1;
        if (t2 < 0 || t2 >= TT_) continue;
        __syncthreads();
        for (int k = tid; k < 4096; k += 256) sw[k] = wX[k*3 + kt];
        for (int cc = 0; cc < 2; cc++) {
            __syncthreads();
            size_t off = (size_t)((b*TT_ + t2)*C_ + cc*32)*HW + i0;
            for (int k = tid; k < 1024; k += 256) {
                int c = k >> 5, f = k & 31;
                ((float4*)ss)[k] = ((const float4*)(g_s + off + c*HW))[f];
            }
            __syncthreads();
#pragma unroll 4
            for (int c = 0; c < 32; c++) {
                ull ap[4];
#pragma unroll
                for (int r = 0; r < 4; r++) {
                    float a = sw[(o0 + r)*C_ + cc*32 + c];
                    ap[r] = pack2(a, a);
                }
                float4 b0 = *(const float4*)&ss[c*128 + tx*8];
                float4 b1 = *(const float4*)&ss[c*128 + tx*8 + 4];
                ull bv0, bv1, bv2, bv3;
                f4_to_2ull(b0, bv0, bv1);
                f4_to_2ull(b1, bv2, bv3);
#pragma unroll
                for (int r = 0; r < 4; r++) {
                    fma2(acc[r][0], ap[r], bv0);
                    fma2(acc[r][1], ap[r], bv1);
                    fma2(acc[r][2], ap[r], bv2);
                    fma2(acc[r][3], ap[r], bv3);
                }
            }
        }
    }
#pragma unroll
    for (int r = 0; r < 4; r++) {
        float2 u0 = unpack2(acc[r][0]), u1 = unpack2(acc[r][1]);
        float2 u2 = unpack2(acc[r][2]), u3 = unpack2(acc[r][3]);
        float* gp = g_xe + (size_t)(n*C_ + o0 + r)*HW + i0 + tx*8;
        *(float4*)gp       = make_float4(fmaxf(u0.x,0.f), fmaxf(u0.y,0.f),
                                         fmaxf(u1.x,0.f), fmaxf(u1.y,0.f));
        *(float4*)(gp + 4) = make_float4(fmaxf(u2.x,0.f), fmaxf(u2.y,0.f),
                                         fmaxf(u3.x,0.f), fmaxf(u3.y,0.f));
    }
}

// ============ K8a: temporal score partials, grid (B_,8) ============
__global__ __launch_bounds__(256) void k_mtp()
{
    int b = blockIdx.x, dc = blockIdx.y;
    int tid = threadIdx.x, lane = tid & 31, warp = tid >> 5;
    int d0 = dc * 8192;
    float acc[64];
#pragma unroll
    for (int a = 0; a < 64; a++) acc[a] = 0.f;

    for (int m = 0; m < 32; m++) {
        int d = d0 + m*256 + tid;
        float v[8];
#pragma unroll
        for (int t = 0; t < 8; t++) v[t] = g_xe[(size_t)(b*TT_ + t)*CHW + d];
#pragma unroll
        for (int t = 0; t < 8; t++)
#pragma unroll
            for (int s = 0; s < 8; s++) acc[t*8 + s] = fmaf(v[t], v[s], acc[t*8 + s]);
    }
#pragma unroll
    for (int a = 0; a < 64; a++) {
#pragma unroll
        for (int off = 16; off > 0; off >>= 1)
            acc[a] += __shfl_xor_sync(0xffffffffu, acc[a], off);
    }
    __shared__ float red[8][64];
    if (lane == 0)
        for (int a = 0; a < 64; a++) red[warp][a] = acc[a];
    __syncthreads();
    if (tid < 64) {
        float s = 0.f;
#pragma unroll
        for (int w = 0; w < 8; w++) s += red[w][tid];
        g_mtp[(b*8 + dc)*64 + tid] = s;
    }
}

// ============ K8b: reduce partials + softmax over b ============
__global__ void k_mt_softmax()
{
    __shared__ float sm[B_][64];
    int tid = threadIdx.x;
    int b = tid >> 6, ts = tid & 63;
    float s = 0.f;
#pragma unroll
    for (int dc = 0; dc < 8; dc++) s += g_mtp[(b*8 + dc)*64 + ts];
    sm[b][ts] = s;
    __syncthreads();
    if (tid < 64) {
        float v[B_];
        float mx = -1e30f;
#pragma unroll
        for (int bb = 0; bb < B_; bb++) { v[bb] = sm[bb][tid]; mx = fmaxf(mx, v[bb]); }
        float ss = 0.f;
#pragma unroll
        for (int bb = 0; bb < B_; bb++) { v[bb] = __expf(v[bb] - mx); ss += v[bb]; }
        float inv = 1.f / ss;
#pragma unroll
        for (int bb = 0; bb < B_; bb++) g_mt[bb*64 + tid] = v[bb] * inv;
    }
}

// ============ K8c: out[b,c,t,i] = sum_s m_t[b,t,s] v[b,s,c,i], grid 256 ============
__global__ __launch_bounds__(256) void k_out(float* __restrict__ out)
{
    int bc = blockIdx.x;
    int b = bc >> 6, c = bc & 63;
    __shared__ float smt[64];
    if (threadIdx.x < 64) smt[threadIdx.x] = g_mt[b*64 + threadIdx.x];
    __syncthreads();
    for (int k = 0; k < 4; k++) {
        int i = k*256 + threadIdx.x;
        float v[8];
#pragma unroll
        for (int s = 0; s < 8; s++)
            v[s] = g_rv[(size_t)((b*TT_ + s)*C_ + c)*HW + i];
#pragma unroll
        for (int t = 0; t < 8; t++) {
            float a = 0.f;
#pragma unroll
            for (int s = 0; s < 8; s++) a = fmaf(smt[t*8 + s], v[s], a);
            out[(size_t)((b*C_ + c)*TT_ + t)*HW + i] = a;
        }
    }
}

// ---------------- launch ----------------
extern "C" void kernel_launch(void* const* d_in, const int* in_sizes, int n_in,
                              void* d_out, int out_size)
{
    const float* x  = (const float*)d_in[0];
    const float* wq = (const float*)d_in[1];
    const float* bq = (const float*)d_in[2];
    const float* wk = (const float*)d_in[3];
    const float* bk = (const float*)d_in[4];
    const float* wv = (const float*)d_in[5];
    const float* bv = (const float*)d_in[6];
    const float* wX = (const float*)d_in[7];
    const float* bX = (const float*)d_in[8];
    float* out = (float*)d_out;
    (void)in_sizes; (void)n_in; (void)out_size;

    cudaFuncSetAttribute(k_qkv, cudaFuncAttributeMaxDynamicSharedMemorySize, 49152);

    k_qkv<<<dim3(N_, 8, 3), 256, 49152>>>(x, wq, bq, wk, bk, wv, bv);
    k_gc<<<dim3(N_, 16), 256>>>();
    k_gc_softmax<<<16, 256>>>();
    k_ac<<<dim3(N_, 16), 256>>>();
    k_ms<<<dim3(8, 8, N_), 256>>>();
    k_sum<<<512, 256>>>();
    k_as<<<dim3(16, N_), 256>>>();
    k_tconv<<<dim3(N_, 8), 256>>>(wX, bX);
    k_mtp<<<dim3(B_, 8), 256>>>();
    k_mt_softmax<<<1, 256>>>();
    k_out<<<256, 256>>>(out);
}